// round 16
// baseline (speedup 1.0000x reference)
#include <cuda_runtime.h>
#include <cstdint>
#include <math.h>

#define EMBED   256
#define HIDDEN  512
#define NB      64
#define LSTEPS  2048

// xp[t][n][h] scratch: 2048*64*512 floats = 256MB
__device__ float g_xp[(size_t)LSTEPS * NB * HIDDEN];

// ---- packed f32x2 helpers (Blackwell) ----
#define FMA_F32X2(acc, a, b) \
    asm("fma.rn.f32x2 %0, %1, %2, %0;" : "+l"(acc) : "l"(a), "l"(b))
#define PACK_F32X2(out, lo, hi) \
    asm("mov.b64 %0, {%1, %2};" : "=l"(out) : "f"(lo), "f"(hi))
#define UNPACK_F32X2(lo, hi, in) \
    asm("mov.b64 {%0, %1}, %2;" : "=f"(lo), "=f"(hi) : "l"(in))

// ============================================================================
// Phase 1: xp[l][n][j] = b_xh[j] + sum_d E[X[n][l]][d] * W_xh[d][j]
// (R6 version — proven ~0.85ms)
// ============================================================================
#define BM 128
#define BN 128
#define BK 16

__global__ void __launch_bounds__(256)
proj_kernel(const int* __restrict__ X, const float* __restrict__ E,
            const float* __restrict__ Wxh, const float* __restrict__ bxh)
{
    __shared__ float As[BK][BM];
    __shared__ float Bs[BK][BN];
    __shared__ int   toks[BM];

    const int tid   = threadIdx.x;
    const int mtile = blockIdx.y;
    const int n     = mtile >> 4;
    const int l0    = (mtile & 15) * BM;
    const int j0    = blockIdx.x * BN;

    if (tid < BM) toks[tid] = X[n * LSTEPS + l0 + tid];
    __syncthreads();

    const int ty = tid >> 4;
    const int tx = tid & 15;

    unsigned long long acc[8][4];
#pragma unroll
    for (int i = 0; i < 8; i++)
#pragma unroll
        for (int j = 0; j < 4; j++) acc[i][j] = 0ULL;

    for (int k0 = 0; k0 < EMBED; k0 += BK) {
#pragma unroll
        for (int u = 0; u < 2; u++) {
            int f  = tid + u * 256;
            int m  = f & 127;
            int kq = f >> 7;
            float4 v = *(const float4*)&E[(size_t)toks[m] * EMBED + k0 + kq * 4];
            As[kq * 4 + 0][m] = v.x;
            As[kq * 4 + 1][m] = v.y;
            As[kq * 4 + 2][m] = v.z;
            As[kq * 4 + 3][m] = v.w;
        }
#pragma unroll
        for (int u = 0; u < 2; u++) {
            int f  = tid + u * 256;
            int kk = f >> 5;
            int jj = (f & 31) * 4;
            *(float4*)&Bs[kk][jj] =
                *(const float4*)&Wxh[(size_t)(k0 + kk) * HIDDEN + j0 + jj];
        }
        __syncthreads();
#pragma unroll
        for (int kk = 0; kk < BK; kk++) {
            float a[8];
            *(float4*)&a[0] = *(const float4*)&As[kk][ty * 8];
            *(float4*)&a[4] = *(const float4*)&As[kk][ty * 8 + 4];
            ulonglong2 b01 = *(const ulonglong2*)&Bs[kk][tx * 8];
            ulonglong2 b23 = *(const ulonglong2*)&Bs[kk][tx * 8 + 4];
            unsigned long long bp[4] = {b01.x, b01.y, b23.x, b23.y};
#pragma unroll
            for (int i = 0; i < 8; i++) {
                unsigned long long aa;
                PACK_F32X2(aa, a[i], a[i]);
#pragma unroll
                for (int j = 0; j < 4; j++)
                    FMA_F32X2(acc[i][j], aa, bp[j]);
            }
        }
        __syncthreads();
    }

    float bx[8];
#pragma unroll
    for (int q = 0; q < 8; q++) bx[q] = bxh[j0 + tx * 8 + q];

#pragma unroll
    for (int i = 0; i < 8; i++) {
        int l = l0 + ty * 8 + i;
        float* dst = g_xp + (size_t)l * (NB * HIDDEN) + n * HIDDEN + j0 + tx * 8;
        float r[8];
#pragma unroll
        for (int j = 0; j < 4; j++) {
            float lo, hi;
            UNPACK_F32X2(lo, hi, acc[i][j]);
            r[j * 2]     = lo + bx[j * 2];
            r[j * 2 + 1] = hi + bx[j * 2 + 1];
        }
        *(float4*)dst       = make_float4(r[0], r[1], r[2], r[3]);
        *(float4*)(dst + 4) = make_float4(r[4], r[5], r[6], r[7]);
    }
}

// ============================================================================
// Phase 2: persistent cluster RNN, 32 clusters x 4 CTAs, PARALLEL-TAILS:
//   wait(1x) -> fmaA -> bar -> fmaB -> bar -> { WG0: tailA || WG1: tailB }
// Both tails occupy the SAME inter-barrier segment on different warp halves,
// so the window is 2F + T instead of R6's 2F + 2T. Single mbar (count 8 =
// 2 arrives/CTA x 4 CTAs) waited once per step; the acquire covers both
// groups' pushes (reads -> bar -> push -> named-bar -> release-arrive chain).
// W layout/split and FMA sections are R6-verbatim.
// ============================================================================
#define CL       4
#define JSL      128
#define REG_IT   20                     // iters 0..19 from regs (80 ull)
#define SMEM_IT  12                     // iters 20..31 from smem (48 ull)

struct SmemR {
    ulonglong2 Wsm[SMEM_IT * 2 * 256];  // [plane][tid] 16B lanes: 98304 B
    float hbuf[2][2][HIDDEN];           // [group][buf][j]         8192 B
    float red[2][4][JSL];               // [group][kg][j]          4096 B
    float bh[JSL];                      //                         512 B
    unsigned long long mb;              // single per-step mbarrier
};
#define SMEMR_BYTES ((int)sizeof(SmemR))

__device__ __forceinline__ uint32_t smem_u32(const void* p) {
    uint32_t a;
    asm("{ .reg .u64 t; cvta.to.shared.u64 t, %1; cvt.u32.u64 %0, t; }"
        : "=r"(a) : "l"(p));
    return a;
}
__device__ __forceinline__ uint32_t mapa_u32(uint32_t a, uint32_t rank) {
    uint32_t r;
    asm("mapa.shared::cluster.u32 %0, %1, %2;" : "=r"(r) : "r"(a), "r"(rank));
    return r;
}
__device__ __forceinline__ void stc_b32(uint32_t a, float v) {
    asm volatile("st.shared::cluster.b32 [%0], %1;"
                 :: "r"(a), "r"(__float_as_uint(v)) : "memory");
}
__device__ __forceinline__ void mbar_init(uint32_t a, uint32_t cnt) {
    asm volatile("mbarrier.init.shared.b64 [%0], %1;" :: "r"(a), "r"(cnt) : "memory");
}
__device__ __forceinline__ void mbar_arrive_remote(uint32_t a) {
    asm volatile("mbarrier.arrive.release.cluster.shared::cluster.b64 _, [%0];"
                 :: "r"(a) : "memory");
}
__device__ __forceinline__ void mbar_wait_parity(uint32_t a, uint32_t parity) {
    asm volatile(
        "{\n\t.reg .pred P;\n\t"
        "WL_%=:\n\t"
        "mbarrier.try_wait.parity.acquire.cluster.shared::cta.b64 P, [%0], %1, 0x989680;\n\t"
        "@!P bra WL_%=;\n\t}"
        :: "r"(a), "r"(parity) : "memory");
}
__device__ __forceinline__ void cluster_sync_() {
    asm volatile("barrier.cluster.arrive.aligned;" ::: "memory");
    asm volatile("barrier.cluster.wait.aligned;" ::: "memory");
}
__device__ __forceinline__ void named_bar(int id) {
    asm volatile("bar.sync %0, 128;" :: "r"(id) : "memory");
}

// tanh = (e-1)/(e+1), e = 2^(2x*log2e); ~1e-6 abs err, branch-free.
__device__ __forceinline__ float fast_tanh(float x) {
    x = fminf(fmaxf(x, -15.0f), 15.0f);
    float e;
    asm("ex2.approx.f32 %0, %1;" : "=f"(e) : "f"(x * 2.8853900817779268f));
    float r;
    asm("rcp.approx.f32 %0, %1;" : "=f"(r) : "f"(e + 1.0f));
    return (e - 1.0f) * r;
}

extern __shared__ float smem_raw[];

__global__ void __cluster_dims__(CL, 1, 1) __launch_bounds__(256, 1)
rnn_kernel(const float* __restrict__ Whh, const float* __restrict__ bhh,
           float* __restrict__ out)
{
    SmemR* s = (SmemR*)smem_raw;
    const int tid  = threadIdx.x;
    const int rank = blockIdx.x;      // 0..3
    const int g    = blockIdx.y;      // 0..31
    const int j0   = rank * JSL;
    const int rowA = 2 * g;

    const int kg = tid >> 6;          // 0..3 : k in [128kg, +128)
    const int jp = tid & 63;          // j-pair: jcol = j0 + jp*2

    // ---- W slice: 80 ull regs (iters 0..19) + 48 ull smem (iters 20..31) ----
    unsigned long long Wr0[2 * REG_IT], Wr1[2 * REG_IT];
    {
        const int kb   = kg * 128;
        const int jcol = j0 + jp * 2;
#pragma unroll
        for (int m = 0; m < 2 * REG_IT; m++) {
            int k = kb + m * 2;
            float2 w0 = *(const float2*)&Whh[(size_t)k * HIDDEN + jcol];
            float2 w1 = *(const float2*)&Whh[(size_t)(k + 1) * HIDDEN + jcol];
            PACK_F32X2(Wr0[m], w0.x, w1.x);
            PACK_F32X2(Wr1[m], w0.y, w1.y);
        }
#pragma unroll
        for (int i = 0; i < SMEM_IT; i++) {
            unsigned long long p0a, p0b, p1a, p1b;
#pragma unroll
            for (int q = 0; q < 2; q++) {
                int m = 2 * (REG_IT + i) + q;
                int k = kb + m * 2;
                float2 w0 = *(const float2*)&Whh[(size_t)k * HIDDEN + jcol];
                float2 w1 = *(const float2*)&Whh[(size_t)(k + 1) * HIDDEN + jcol];
                unsigned long long u0, u1;
                PACK_F32X2(u0, w0.x, w1.x);
                PACK_F32X2(u1, w0.y, w1.y);
                if (q == 0) { p0a = u0; p1a = u1; }
                else        { p0b = u0; p1b = u1; }
            }
            s->Wsm[(i * 2 + 0) * 256 + tid] = make_ulonglong2(p0a, p0b);
            s->Wsm[(i * 2 + 1) * 256 + tid] = make_ulonglong2(p1a, p1b);
        }
    }

    // ---- smem init ----
    for (int idx = tid; idx < 2 * 2 * HIDDEN; idx += 256)
        ((float*)s->hbuf)[idx] = 0.f;
    if (tid < JSL) s->bh[tid] = bhh[j0 + tid];

    const uint32_t s_base = smem_u32(s);
    const uint32_t hbA    = smem_u32(&s->hbuf[0][0][0]) - s_base;
    const uint32_t hbB    = smem_u32(&s->hbuf[1][0][0]) - s_base;
    const uint32_t mb_off = smem_u32(&s->mb) - s_base;

    uint32_t peer_base[CL];
#pragma unroll
    for (int r = 0; r < CL; r++) peer_base[r] = mapa_u32(s_base, (uint32_t)r);

    if (tid == 0) {
        mbar_init(s_base + mb_off, 2 * CL);   // 2 arrives/CTA x 4 CTAs
        asm volatile("fence.mbarrier_init.release.cluster;" ::: "memory");
    }
    __syncthreads();
    cluster_sync_();   // W/h/bh/mbar visible cluster-wide

    // tail role: thread (half = tid>>7) reduces group `half`, column rj
    const int half = tid >> 7;        // 0 -> tailA, 1 -> tailB
    const int rj   = tid & 127;
    const int myrow = rowA + half;
    const uint32_t my_hb = half ? hbB : hbA;

    const size_t xstride = (size_t)NB * HIDDEN;
    const float* xp = g_xp + (size_t)myrow * HIDDEN + j0 + rj;
    float xcur = __ldcs(xp);
    const float* xnp = xp + xstride;

    const ulonglong2* WsmT = &s->Wsm[tid];     // plane p at WsmT[p*256]

    for (int t = 0; t < LSTEPS; t++) {
        const int cur = t & 1;
        const int nxt = cur ^ 1;
        const uint32_t pw = (uint32_t)((t & 1) ^ 1);   // parity of step t-1
        const bool last = (t == LSTEPS - 1);
        float xnx = last ? 0.f : __ldcs(xnp);

        if (t) mbar_wait_parity(s_base + mb_off, pw);  // covers BOTH groups

        // ---- two FMA sections, back-to-back (no tails between) ----
#pragma unroll 1
        for (int grp = 0; grp < 2; grp++) {
            const ulonglong2* hv =
                (const ulonglong2*)&s->hbuf[grp][cur][kg * 128];
            unsigned long long a0 = 0ULL, a1 = 0ULL;
#pragma unroll
            for (int i = 0; i < REG_IT; i++) {
                ulonglong2 h = hv[i];
                FMA_F32X2(a0, Wr0[2 * i],     h.x);
                FMA_F32X2(a0, Wr0[2 * i + 1], h.y);
                FMA_F32X2(a1, Wr1[2 * i],     h.x);
                FMA_F32X2(a1, Wr1[2 * i + 1], h.y);
            }
#pragma unroll
            for (int i = 0; i < SMEM_IT; i++) {
                ulonglong2 h  = hv[REG_IT + i];
                ulonglong2 w0 = WsmT[(i * 2 + 0) * 256];
                ulonglong2 w1 = WsmT[(i * 2 + 1) * 256];
                FMA_F32X2(a0, w0.x, h.x);
                FMA_F32X2(a0, w0.y, h.y);
                FMA_F32X2(a1, w1.x, h.x);
                FMA_F32X2(a1, w1.y, h.y);
            }
            {
                float lo, hi, f0, f1;
                UNPACK_F32X2(lo, hi, a0); f0 = lo + hi;
                UNPACK_F32X2(lo, hi, a1); f1 = lo + hi;
                *(float2*)&s->red[grp][kg][jp * 2] = make_float2(f0, f1);
            }
            __syncthreads();
        }

        // ---- parallel tails: WG0 finalizes row A, WG1 row B ----
        {
            float sum = s->bh[rj] + xcur
                      + s->red[half][0][rj] + s->red[half][1][rj]
                      + s->red[half][2][rj] + s->red[half][3][rj];
            float hn = fast_tanh(sum);

            if (last) {
                out[myrow * HIDDEN + j0 + rj] = hn;
            } else {
                const uint32_t off = my_hb +
                    (uint32_t)((nxt * HIDDEN + j0 + rj) * 4);
#pragma unroll
                for (int r = 0; r < CL; r++)
                    stc_b32(peer_base[r] + off, hn);
                named_bar(1 + half);              // order pushes, own half only
                if (rj < CL)
                    mbar_arrive_remote(peer_base[rj] + mb_off);
            }
        }

        xcur = xnx;
        xnp += xstride;
    }
}

// ============================================================================
extern "C" void kernel_launch(void* const* d_in, const int* in_sizes, int n_in,
                              void* d_out, int out_size)
{
    const int*   X   = (const int*)d_in[0];
    const float* E   = (const float*)d_in[1];
    const float* Whh = (const float*)d_in[2];
    const float* bhh = (const float*)d_in[3];
    const float* Wxh = (const float*)d_in[4];
    const float* bxh = (const float*)d_in[5];
    float* out = (float*)d_out;

    cudaFuncSetAttribute(rnn_kernel,
                         cudaFuncAttributeMaxDynamicSharedMemorySize,
                         SMEMR_BYTES);

    proj_kernel<<<dim3(4, 1024), 256>>>(X, E, Wxh, bxh);
    rnn_kernel<<<dim3(CL, NB / 2), 256, SMEMR_BYTES>>>(Whh, bhh, out);
}

// round 17
// speedup vs baseline: 1.1141x; 1.1141x over previous
#include <cuda_runtime.h>
#include <cstdint>
#include <math.h>

#define EMBED   256
#define HIDDEN  512
#define NB      64
#define LSTEPS  2048

// xp[t][n][h] scratch: 2048*64*512 floats = 256MB
__device__ float g_xp[(size_t)LSTEPS * NB * HIDDEN];

// ---- packed f32x2 helpers (Blackwell) ----
#define FMA_F32X2(acc, a, b) \
    asm("fma.rn.f32x2 %0, %1, %2, %0;" : "+l"(acc) : "l"(a), "l"(b))
#define PACK_F32X2(out, lo, hi) \
    asm("mov.b64 %0, {%1, %2};" : "=l"(out) : "f"(lo), "f"(hi))
#define UNPACK_F32X2(lo, hi, in) \
    asm("mov.b64 {%0, %1}, %2;" : "=f"(lo), "=f"(hi) : "l"(in))

// ============================================================================
// Phase 1: xp[l][n][j] = b_xh[j] + sum_d E[X[n][l]][d] * W_xh[d][j]
// (R6 version — proven ~0.85ms)
// ============================================================================
#define BM 128
#define BN 128
#define BK 16

__global__ void __launch_bounds__(256)
proj_kernel(const int* __restrict__ X, const float* __restrict__ E,
            const float* __restrict__ Wxh, const float* __restrict__ bxh)
{
    __shared__ float As[BK][BM];
    __shared__ float Bs[BK][BN];
    __shared__ int   toks[BM];

    const int tid   = threadIdx.x;
    const int mtile = blockIdx.y;
    const int n     = mtile >> 4;
    const int l0    = (mtile & 15) * BM;
    const int j0    = blockIdx.x * BN;

    if (tid < BM) toks[tid] = X[n * LSTEPS + l0 + tid];
    __syncthreads();

    const int ty = tid >> 4;
    const int tx = tid & 15;

    unsigned long long acc[8][4];
#pragma unroll
    for (int i = 0; i < 8; i++)
#pragma unroll
        for (int j = 0; j < 4; j++) acc[i][j] = 0ULL;

    for (int k0 = 0; k0 < EMBED; k0 += BK) {
#pragma unroll
        for (int u = 0; u < 2; u++) {
            int f  = tid + u * 256;
            int m  = f & 127;
            int kq = f >> 7;
            float4 v = *(const float4*)&E[(size_t)toks[m] * EMBED + k0 + kq * 4];
            As[kq * 4 + 0][m] = v.x;
            As[kq * 4 + 1][m] = v.y;
            As[kq * 4 + 2][m] = v.z;
            As[kq * 4 + 3][m] = v.w;
        }
#pragma unroll
        for (int u = 0; u < 2; u++) {
            int f  = tid + u * 256;
            int kk = f >> 5;
            int jj = (f & 31) * 4;
            *(float4*)&Bs[kk][jj] =
                *(const float4*)&Wxh[(size_t)(k0 + kk) * HIDDEN + j0 + jj];
        }
        __syncthreads();
#pragma unroll
        for (int kk = 0; kk < BK; kk++) {
            float a[8];
            *(float4*)&a[0] = *(const float4*)&As[kk][ty * 8];
            *(float4*)&a[4] = *(const float4*)&As[kk][ty * 8 + 4];
            ulonglong2 b01 = *(const ulonglong2*)&Bs[kk][tx * 8];
            ulonglong2 b23 = *(const ulonglong2*)&Bs[kk][tx * 8 + 4];
            unsigned long long bp[4] = {b01.x, b01.y, b23.x, b23.y};
#pragma unroll
            for (int i = 0; i < 8; i++) {
                unsigned long long aa;
                PACK_F32X2(aa, a[i], a[i]);
#pragma unroll
                for (int j = 0; j < 4; j++)
                    FMA_F32X2(acc[i][j], aa, bp[j]);
            }
        }
        __syncthreads();
    }

    float bx[8];
#pragma unroll
    for (int q = 0; q < 8; q++) bx[q] = bxh[j0 + tx * 8 + q];

#pragma unroll
    for (int i = 0; i < 8; i++) {
        int l = l0 + ty * 8 + i;
        float* dst = g_xp + (size_t)l * (NB * HIDDEN) + n * HIDDEN + j0 + tx * 8;
        float r[8];
#pragma unroll
        for (int j = 0; j < 4; j++) {
            float lo, hi;
            UNPACK_F32X2(lo, hi, acc[i][j]);
            r[j * 2]     = lo + bx[j * 2];
            r[j * 2 + 1] = hi + bx[j * 2 + 1];
        }
        *(float4*)dst       = make_float4(r[0], r[1], r[2], r[3]);
        *(float4*)(dst + 4) = make_float4(r[4], r[5], r[6], r[7]);
    }
}

// ============================================================================
// Phase 2: persistent cluster RNN, 32 clusters x 4 CTAs.
// FUSED-SMEM variant of R6: W is group-independent, so the smem-W portion
// of both group sections shares each Wsm load (Wsm crossbar HALVED):
//   waitA -> fmaA_reg -> waitB -> fused_smem(A+B) -> fmaB_reg
//   -> red stores -> bar -> tails A||B (per-half; per-group mbar arrives)
// Per-group waits preserved (R16 showed combining them costs ~300cyc).
// red[] double-buffered by step parity (no 2nd block barrier needed).
// ============================================================================
#define CL       4
#define JSL      128
#define REG_IT   20                     // iters 0..19 from regs (80 ull)
#define SMEM_IT  12                     // iters 20..31 from smem (48 ull)

struct SmemR {
    ulonglong2 Wsm[SMEM_IT * 2 * 256];  // [plane][tid] 16B lanes: 98304 B
    float hbuf[2][2][HIDDEN];           // [group][buf][j]          8192 B
    float red[2][2][4][JSL];            // [parity][group][kg][j]   8192 B
    float bh[JSL];                      //                           512 B
    unsigned long long mb[2];           // per-group mbarrier
};
#define SMEMR_BYTES ((int)sizeof(SmemR))

__device__ __forceinline__ uint32_t smem_u32(const void* p) {
    uint32_t a;
    asm("{ .reg .u64 t; cvta.to.shared.u64 t, %1; cvt.u32.u64 %0, t; }"
        : "=r"(a) : "l"(p));
    return a;
}
__device__ __forceinline__ uint32_t mapa_u32(uint32_t a, uint32_t rank) {
    uint32_t r;
    asm("mapa.shared::cluster.u32 %0, %1, %2;" : "=r"(r) : "r"(a), "r"(rank));
    return r;
}
__device__ __forceinline__ void stc_b32(uint32_t a, float v) {
    asm volatile("st.shared::cluster.b32 [%0], %1;"
                 :: "r"(a), "r"(__float_as_uint(v)) : "memory");
}
__device__ __forceinline__ void mbar_init(uint32_t a, uint32_t cnt) {
    asm volatile("mbarrier.init.shared.b64 [%0], %1;" :: "r"(a), "r"(cnt) : "memory");
}
__device__ __forceinline__ void mbar_arrive_remote(uint32_t a) {
    asm volatile("mbarrier.arrive.release.cluster.shared::cluster.b64 _, [%0];"
                 :: "r"(a) : "memory");
}
__device__ __forceinline__ void mbar_wait_parity(uint32_t a, uint32_t parity) {
    asm volatile(
        "{\n\t.reg .pred P;\n\t"
        "WL_%=:\n\t"
        "mbarrier.try_wait.parity.acquire.cluster.shared::cta.b64 P, [%0], %1, 0x989680;\n\t"
        "@!P bra WL_%=;\n\t}"
        :: "r"(a), "r"(parity) : "memory");
}
__device__ __forceinline__ void cluster_sync_() {
    asm volatile("barrier.cluster.arrive.aligned;" ::: "memory");
    asm volatile("barrier.cluster.wait.aligned;" ::: "memory");
}
__device__ __forceinline__ void named_bar(int id) {
    asm volatile("bar.sync %0, 128;" :: "r"(id) : "memory");
}

// tanh = (e-1)/(e+1), e = 2^(2x*log2e); ~1e-6 abs err, branch-free.
__device__ __forceinline__ float fast_tanh(float x) {
    x = fminf(fmaxf(x, -15.0f), 15.0f);
    float e;
    asm("ex2.approx.f32 %0, %1;" : "=f"(e) : "f"(x * 2.8853900817779268f));
    float r;
    asm("rcp.approx.f32 %0, %1;" : "=f"(r) : "f"(e + 1.0f));
    return (e - 1.0f) * r;
}

extern __shared__ float smem_raw[];

__global__ void __cluster_dims__(CL, 1, 1) __launch_bounds__(256, 1)
rnn_kernel(const float* __restrict__ Whh, const float* __restrict__ bhh,
           float* __restrict__ out)
{
    SmemR* s = (SmemR*)smem_raw;
    const int tid  = threadIdx.x;
    const int rank = blockIdx.x;      // 0..3
    const int g    = blockIdx.y;      // 0..31
    const int j0   = rank * JSL;
    const int rowA = 2 * g;

    const int kg = tid >> 6;          // 0..3 : k in [128kg, +128)
    const int jp = tid & 63;          // j-pair: jcol = j0 + jp*2

    // ---- W slice: 80 ull regs (iters 0..19) + 48 ull smem (iters 20..31) ----
    unsigned long long Wr0[2 * REG_IT], Wr1[2 * REG_IT];
    {
        const int kb   = kg * 128;
        const int jcol = j0 + jp * 2;
#pragma unroll
        for (int m = 0; m < 2 * REG_IT; m++) {
            int k = kb + m * 2;
            float2 w0 = *(const float2*)&Whh[(size_t)k * HIDDEN + jcol];
            float2 w1 = *(const float2*)&Whh[(size_t)(k + 1) * HIDDEN + jcol];
            PACK_F32X2(Wr0[m], w0.x, w1.x);
            PACK_F32X2(Wr1[m], w0.y, w1.y);
        }
#pragma unroll
        for (int i = 0; i < SMEM_IT; i++) {
            unsigned long long p0a, p0b, p1a, p1b;
#pragma unroll
            for (int q = 0; q < 2; q++) {
                int m = 2 * (REG_IT + i) + q;
                int k = kb + m * 2;
                float2 w0 = *(const float2*)&Whh[(size_t)k * HIDDEN + jcol];
                float2 w1 = *(const float2*)&Whh[(size_t)(k + 1) * HIDDEN + jcol];
                unsigned long long u0, u1;
                PACK_F32X2(u0, w0.x, w1.x);
                PACK_F32X2(u1, w0.y, w1.y);
                if (q == 0) { p0a = u0; p1a = u1; }
                else        { p0b = u0; p1b = u1; }
            }
            s->Wsm[(i * 2 + 0) * 256 + tid] = make_ulonglong2(p0a, p0b);
            s->Wsm[(i * 2 + 1) * 256 + tid] = make_ulonglong2(p1a, p1b);
        }
    }

    // ---- smem init ----
    for (int idx = tid; idx < 2 * 2 * HIDDEN; idx += 256)
        ((float*)s->hbuf)[idx] = 0.f;
    if (tid < JSL) s->bh[tid] = bhh[j0 + tid];

    const uint32_t s_base = smem_u32(s);
    const uint32_t hbA    = smem_u32(&s->hbuf[0][0][0]) - s_base;
    const uint32_t hbB    = smem_u32(&s->hbuf[1][0][0]) - s_base;
    const uint32_t mbA    = smem_u32(&s->mb[0]) - s_base;
    const uint32_t mbB    = smem_u32(&s->mb[1]) - s_base;

    uint32_t peer_base[CL];
#pragma unroll
    for (int r = 0; r < CL; r++) peer_base[r] = mapa_u32(s_base, (uint32_t)r);

    if (tid == 0) {
        mbar_init(s_base + mbA, CL);   // 1 arrive per CTA per step
        mbar_init(s_base + mbB, CL);
        asm volatile("fence.mbarrier_init.release.cluster;" ::: "memory");
    }
    __syncthreads();
    cluster_sync_();   // W/h/bh/mbar visible cluster-wide

    // tail role: thread (half = tid>>7) finalizes group `half`, column rj
    const int half = tid >> 7;        // 0 -> tail A, 1 -> tail B
    const int rj   = tid & 127;
    const int myrow = rowA + half;
    const uint32_t my_hb = half ? hbB : hbA;
    const uint32_t my_mb = half ? mbB : mbA;

    const size_t xstride = (size_t)NB * HIDDEN;
    const float* xp = g_xp + (size_t)myrow * HIDDEN + j0 + rj;
    float xcur = __ldcs(xp);
    const float* xnp = xp + xstride;

    const ulonglong2* WsmT = &s->Wsm[tid];     // plane p at WsmT[p*256]

    for (int t = 0; t < LSTEPS; t++) {
        const int cur = t & 1;
        const int nxt = cur ^ 1;
        const int pr  = t & 1;                         // red parity buffer
        const uint32_t pw = (uint32_t)((t & 1) ^ 1);   // parity of step t-1
        const bool last = (t == LSTEPS - 1);
        float xnx = last ? 0.f : __ldcs(xnp);

        const ulonglong2* hvA =
            (const ulonglong2*)&s->hbuf[0][cur][kg * 128];
        const ulonglong2* hvB =
            (const ulonglong2*)&s->hbuf[1][cur][kg * 128];

        unsigned long long aA0 = 0ULL, aA1 = 0ULL, aB0 = 0ULL, aB1 = 0ULL;

        // ---- group A register-W portion (overlaps group B's flight) ----
        if (t) mbar_wait_parity(s_base + mbA, pw);
#pragma unroll
        for (int i = 0; i < REG_IT; i++) {
            ulonglong2 h = hvA[i];
            FMA_F32X2(aA0, Wr0[2 * i],     h.x);
            FMA_F32X2(aA0, Wr0[2 * i + 1], h.y);
            FMA_F32X2(aA1, Wr1[2 * i],     h.x);
            FMA_F32X2(aA1, Wr1[2 * i + 1], h.y);
        }

        // ---- fused smem-W portion: ONE Wsm stream feeds both groups ----
        if (t) mbar_wait_parity(s_base + mbB, pw);
#pragma unroll
        for (int i = 0; i < SMEM_IT; i++) {
            ulonglong2 w0 = WsmT[(i * 2 + 0) * 256];
            ulonglong2 w1 = WsmT[(i * 2 + 1) * 256];
            ulonglong2 ha = hvA[REG_IT + i];
            ulonglong2 hb = hvB[REG_IT + i];
            FMA_F32X2(aA0, w0.x, ha.x);
            FMA_F32X2(aA0, w0.y, ha.y);
            FMA_F32X2(aA1, w1.x, ha.x);
            FMA_F32X2(aA1, w1.y, ha.y);
            FMA_F32X2(aB0, w0.x, hb.x);
            FMA_F32X2(aB0, w0.y, hb.y);
            FMA_F32X2(aB1, w1.x, hb.x);
            FMA_F32X2(aB1, w1.y, hb.y);
        }

        // ---- group B register-W portion ----
#pragma unroll
        for (int i = 0; i < REG_IT; i++) {
            ulonglong2 h = hvB[i];
            FMA_F32X2(aB0, Wr0[2 * i],     h.x);
            FMA_F32X2(aB0, Wr0[2 * i + 1], h.y);
            FMA_F32X2(aB1, Wr1[2 * i],     h.x);
            FMA_F32X2(aB1, Wr1[2 * i + 1], h.y);
        }

        // ---- red stores (parity buffer pr) ----
        {
            float lo, hi, f0, f1;
            UNPACK_F32X2(lo, hi, aA0); f0 = lo + hi;
            UNPACK_F32X2(lo, hi, aA1); f1 = lo + hi;
            *(float2*)&s->red[pr][0][kg][jp * 2] = make_float2(f0, f1);
            UNPACK_F32X2(lo, hi, aB0); f0 = lo + hi;
            UNPACK_F32X2(lo, hi, aB1); f1 = lo + hi;
            *(float2*)&s->red[pr][1][kg][jp * 2] = make_float2(f0, f1);
        }
        __syncthreads();   // all hbuf reads + red stores done

        // ---- parallel tails: half 0 -> row A, half 1 -> row B ----
        {
            float sum = s->bh[rj] + xcur
                      + s->red[pr][half][0][rj] + s->red[pr][half][1][rj]
                      + s->red[pr][half][2][rj] + s->red[pr][half][3][rj];
            float hn = fast_tanh(sum);

            if (last) {
                out[myrow * HIDDEN + j0 + rj] = hn;
            } else {
                const uint32_t off = my_hb +
                    (uint32_t)((nxt * HIDDEN + j0 + rj) * 4);
#pragma unroll
                for (int r = 0; r < CL; r++)
                    stc_b32(peer_base[r] + off, hn);
                named_bar(1 + half);              // order own half's pushes
                if (rj < CL)
                    mbar_arrive_remote(peer_base[rj] + my_mb);
            }
        }

        xcur = xnx;
        xnp += xstride;
    }
}

// ============================================================================
extern "C" void kernel_launch(void* const* d_in, const int* in_sizes, int n_in,
                              void* d_out, int out_size)
{
    const int*   X   = (const int*)d_in[0];
    const float* E   = (const float*)d_in[1];
    const float* Whh = (const float*)d_in[2];
    const float* bhh = (const float*)d_in[3];
    const float* Wxh = (const float*)d_in[4];
    const float* bxh = (const float*)d_in[5];
    float* out = (float*)d_out;

    cudaFuncSetAttribute(rnn_kernel,
                         cudaFuncAttributeMaxDynamicSharedMemorySize,
                         SMEMR_BYTES);

    proj_kernel<<<dim3(4, 1024), 256>>>(X, E, Wxh, bxh);
    rnn_kernel<<<dim3(CL, NB / 2), 256, SMEMR_BYTES>>>(Whh, bhh, out);
}